// round 13
// baseline (speedup 1.0000x reference)
#include <cuda_runtime.h>
#include <cstdint>

#define NTOK   4096
#define DMODEL 1024
#define NEXP   8
#define TOPK   2
#define HEXP   704
#define HSH    1408
#define BK     16

// ---------------- scratch (device globals; no allocation allowed) ----------
__device__ int   g_cnt[NEXP];
__device__ int   g_off[NEXP + 1];
__device__ int   g_topi[NTOK * TOPK];
__device__ float g_topw[NTOK * TOPK];
__device__ int   g_tok[NTOK * TOPK];
__device__ float g_gate[NTOK * TOPK];
__device__ float g_hid_r[NTOK * TOPK * HEXP];   // routed SwiGLU hidden
__device__ float g_hid_s[NTOK * HSH];           // shared-expert hidden

// ---------------- setup kernels ---------------------------------------------
__global__ void zero_kernel() {
    int t = threadIdx.x;
    if (t < NEXP) g_cnt[t] = 0;
}

__global__ void router_kernel(const float* __restrict__ x,
                              const float* __restrict__ Wg) {
    int gw   = (blockIdx.x * blockDim.x + threadIdx.x) >> 5;
    int lane = threadIdx.x & 31;
    if (gw >= NTOK) return;
    const float* xr = x + (size_t)gw * DMODEL;

    float acc[NEXP];
#pragma unroll
    for (int e = 0; e < NEXP; e++) acc[e] = 0.f;
    for (int k = lane; k < DMODEL; k += 32) {
        float xv = xr[k];
#pragma unroll
        for (int e = 0; e < NEXP; e++) acc[e] += xv * Wg[e * DMODEL + k];
    }
#pragma unroll
    for (int e = 0; e < NEXP; e++) {
#pragma unroll
        for (int o = 16; o > 0; o >>= 1)
            acc[e] += __shfl_xor_sync(0xffffffffu, acc[e], o);
    }
    if (lane == 0) {
        float m = acc[0];
#pragma unroll
        for (int e = 1; e < NEXP; e++) m = fmaxf(m, acc[e]);
        float p[NEXP], s = 0.f;
#pragma unroll
        for (int e = 0; e < NEXP; e++) { p[e] = expf(acc[e] - m); s += p[e]; }
        float inv = 1.f / s;
#pragma unroll
        for (int e = 0; e < NEXP; e++) p[e] *= inv;

        int i0 = 0; float v0 = p[0];
#pragma unroll
        for (int e = 1; e < NEXP; e++) if (p[e] > v0) { v0 = p[e]; i0 = e; }
        int i1 = (i0 == 0) ? 1 : 0; float v1 = p[i1];
#pragma unroll
        for (int e = 0; e < NEXP; e++)
            if (e != i0 && p[e] > v1) { v1 = p[e]; i1 = e; }

        float sw = v0 + v1 + 1e-20f;
        g_topi[gw * 2] = i0;  g_topi[gw * 2 + 1] = i1;
        g_topw[gw * 2] = v0 / sw;  g_topw[gw * 2 + 1] = v1 / sw;
        atomicAdd(&g_cnt[i0], 1);
        atomicAdd(&g_cnt[i1], 1);
    }
}

// single block: exclusive scan of g_cnt, then scatter fill
__global__ void scanfill_kernel() {
    __shared__ int s_off[NEXP + 1];
    __shared__ int s_cur[NEXP];
    int tid = threadIdx.x;
    if (tid == 0) {
        int acc = 0;
        s_off[0] = 0;
        for (int e = 0; e < NEXP; e++) {
            acc += g_cnt[e];
            s_off[e + 1] = acc;
            s_cur[e] = 0;
        }
        for (int e = 0; e <= NEXP; e++) g_off[e] = s_off[e];
    }
    __syncthreads();
    for (int n = tid; n < NTOK; n += blockDim.x) {
#pragma unroll
        for (int s = 0; s < TOPK; s++) {
            int e   = g_topi[n * 2 + s];
            int pos = atomicAdd(&s_cur[e], 1);
            int idx = s_off[e] + pos;
            g_tok[idx]  = n;
            g_gate[idx] = g_topw[n * 2 + s];
        }
    }
}

__device__ __forceinline__ float silu_f(float z) {
    return z / (1.f + __expf(-z));
}

// ============ GEMM1 fused: hid = silu(A@W1)*(A@W3) ==========================
// grid (11, 64, 10). CTA 64x64, 128 threads = 16(ty) x 8(tx),
// thread tile 4 rows x (8+8) split-cols per matrix pair (64 accs, no spill).
// Double-buffered smem, 1 sync/tile.
__global__ __launch_bounds__(128, 3)
void gemm1_all(const float* __restrict__ x,
               const float* __restrict__ W1,
               const float* __restrict__ W3,
               const float* __restrict__ Ws1,
               const float* __restrict__ Ws3) {
    int z = blockIdx.z;
    bool routed = (z < NEXP);
    int base = 0, ne = NTOK, H, n0;
    const float *B1, *B3;
    float* hid;
    if (routed) {
        base = g_off[z]; ne = g_off[z + 1] - base;
        H = HEXP; hid = g_hid_r;
        n0 = blockIdx.x * 64;
        B1 = W1 + (size_t)z * DMODEL * HEXP + n0;
        B3 = W3 + (size_t)z * DMODEL * HEXP + n0;
    } else {
        H = HSH; hid = g_hid_s;
        n0 = (blockIdx.x + (z - NEXP) * 11) * 64;
        B1 = Ws1 + n0;
        B3 = Ws3 + n0;
    }
    int m0 = blockIdx.y * 64;
    if (m0 >= ne) return;

    __shared__ float As[2][BK][68];
    __shared__ float Bs1[2][BK][64];
    __shared__ float Bs3[2][BK][64];
    __shared__ int   stok[64];

    int tid = threadIdx.x;
    if (tid < 64)
        stok[tid] = routed ? ((m0 + tid < ne) ? g_tok[base + m0 + tid] : -1)
                           : (m0 + tid);
    __syncthreads();

    // A loader: row = tid>>1 (0..63), k-octet = (tid&1)*8 (2 float4)
    int ar = tid >> 1, ac = (tid & 1) * 8;
    int tk = stok[ar];
    bool aok = (tk >= 0);
    const float* Arow = x + (size_t)(aok ? tk : 0) * DMODEL;
    // B loader: k = tid>>3 (0..15), n-octet = (tid&7)*8 (2 float4 per matrix)
    int br = tid >> 3, bc = (tid & 7) * 8;

    float4 av0 = make_float4(0, 0, 0, 0), av1 = make_float4(0, 0, 0, 0);
    if (aok) {
        av0 = *(const float4*)(Arow + ac);
        av1 = *(const float4*)(Arow + ac + 4);
    }
    float4 b1a = *(const float4*)(B1 + (size_t)br * H + bc);
    float4 b1b = *(const float4*)(B1 + (size_t)br * H + bc + 4);
    float4 b3a = *(const float4*)(B3 + (size_t)br * H + bc);
    float4 b3b = *(const float4*)(B3 + (size_t)br * H + bc + 4);

    As[0][ac + 0][ar] = av0.x; As[0][ac + 1][ar] = av0.y;
    As[0][ac + 2][ar] = av0.z; As[0][ac + 3][ar] = av0.w;
    As[0][ac + 4][ar] = av1.x; As[0][ac + 5][ar] = av1.y;
    As[0][ac + 6][ar] = av1.z; As[0][ac + 7][ar] = av1.w;
    *(float4*)&Bs1[0][br][bc]     = b1a;
    *(float4*)&Bs1[0][br][bc + 4] = b1b;
    *(float4*)&Bs3[0][br][bc]     = b3a;
    *(float4*)&Bs3[0][br][bc + 4] = b3b;
    __syncthreads();

    int ty = tid >> 3, tx = tid & 7;
    int trow = ty * 4, tc = tx * 4;
    float acc1[4][8] = {}, acc3[4][8] = {};

    const int NT = DMODEL / BK;
    for (int t = 0; t < NT; t++) {
        int buf = t & 1;
        int kn  = (t + 1) * BK;
        if (kn < DMODEL) {
            if (aok) {
                av0 = *(const float4*)(Arow + kn + ac);
                av1 = *(const float4*)(Arow + kn + ac + 4);
            }
            b1a = *(const float4*)(B1 + (size_t)(kn + br) * H + bc);
            b1b = *(const float4*)(B1 + (size_t)(kn + br) * H + bc + 4);
            b3a = *(const float4*)(B3 + (size_t)(kn + br) * H + bc);
            b3b = *(const float4*)(B3 + (size_t)(kn + br) * H + bc + 4);
        }
#pragma unroll
        for (int k = 0; k < BK; k++) {
            float4 a  = *(const float4*)&As[buf][k][trow];
            float4 p0 = *(const float4*)&Bs1[buf][k][tc];
            float4 p1 = *(const float4*)&Bs1[buf][k][tc + 32];
            float4 q0 = *(const float4*)&Bs3[buf][k][tc];
            float4 q1 = *(const float4*)&Bs3[buf][k][tc + 32];
            float aa[4] = { a.x, a.y, a.z, a.w };
            float pp[8] = { p0.x, p0.y, p0.z, p0.w, p1.x, p1.y, p1.z, p1.w };
            float qq[8] = { q0.x, q0.y, q0.z, q0.w, q1.x, q1.y, q1.z, q1.w };
#pragma unroll
            for (int i = 0; i < 4; i++)
#pragma unroll
                for (int j = 0; j < 8; j++) {
                    acc1[i][j] = fmaf(aa[i], pp[j], acc1[i][j]);
                    acc3[i][j] = fmaf(aa[i], qq[j], acc3[i][j]);
                }
        }
        if (kn < DMODEL) {
            int nb = buf ^ 1;
            As[nb][ac + 0][ar] = av0.x; As[nb][ac + 1][ar] = av0.y;
            As[nb][ac + 2][ar] = av0.z; As[nb][ac + 3][ar] = av0.w;
            As[nb][ac + 4][ar] = av1.x; As[nb][ac + 5][ar] = av1.y;
            As[nb][ac + 6][ar] = av1.z; As[nb][ac + 7][ar] = av1.w;
            *(float4*)&Bs1[nb][br][bc]     = b1a;
            *(float4*)&Bs1[nb][br][bc + 4] = b1b;
            *(float4*)&Bs3[nb][br][bc]     = b3a;
            *(float4*)&Bs3[nb][br][bc + 4] = b3b;
        }
        __syncthreads();
    }

#pragma unroll
    for (int i = 0; i < 4; i++) {
        int r = trow + i;
        if (m0 + r < ne) {
            size_t rowoff = (size_t)(base + m0 + r) * H + n0;
            float4 h0, h1;
            h0.x = silu_f(acc1[i][0]) * acc3[i][0];
            h0.y = silu_f(acc1[i][1]) * acc3[i][1];
            h0.z = silu_f(acc1[i][2]) * acc3[i][2];
            h0.w = silu_f(acc1[i][3]) * acc3[i][3];
            h1.x = silu_f(acc1[i][4]) * acc3[i][4];
            h1.y = silu_f(acc1[i][5]) * acc3[i][5];
            h1.z = silu_f(acc1[i][6]) * acc3[i][6];
            h1.w = silu_f(acc1[i][7]) * acc3[i][7];
            *(float4*)&hid[rowoff + tc]      = h0;
            *(float4*)&hid[rowoff + tc + 32] = h1;
        }
    }
}

// ============ GEMM2 fused: out += w * (hid @ W2) ============================
// grid (8, 64, 9). CTA 64x128, thread tile 4x(4+4) split-col,
// 256 thr = 16(ty) x 16(tx). out pre-zeroed, all paths atomicAdd.
__global__ __launch_bounds__(256)
void gemm2_all(const float* __restrict__ W2,
               const float* __restrict__ Ws2,
               float* __restrict__ out) {
    int z = blockIdx.z;
    bool routed = (z < NEXP);
    int base = 0, ne = NTOK, K;
    const float* Bp;
    const float* hidg;
    int n0 = blockIdx.x * 128;
    if (routed) {
        base = g_off[z]; ne = g_off[z + 1] - base;
        K = HEXP; hidg = g_hid_r;
        Bp = W2 + (size_t)z * HEXP * DMODEL + n0;
    } else {
        K = HSH; hidg = g_hid_s;
        Bp = Ws2 + n0;
    }
    int m0 = blockIdx.y * 64;
    if (m0 >= ne) return;

    __shared__ float As[2][BK][68];
    __shared__ float Bs[2][BK][128];
    __shared__ int   stok[64];
    __shared__ float sgate[64];

    int tid = threadIdx.x;
    if (tid < 64) {
        if (routed) {
            bool v = (m0 + tid < ne);
            stok[tid]  = v ? g_tok[base + m0 + tid] : 0;
            sgate[tid] = v ? g_gate[base + m0 + tid] : 0.f;
        } else {
            stok[tid]  = m0 + tid;
            sgate[tid] = 1.f;
        }
    }
    __syncthreads();

    int ar = tid >> 2, ac = (tid & 3) * 4;
    bool aok = (m0 + ar < ne);
    const float* Arow = hidg + (size_t)(base + m0 + (aok ? ar : 0)) * K;
    int br = tid >> 4, bc = (tid & 15) * 4;

    float4 av = aok ? *(const float4*)(Arow + ac) : make_float4(0, 0, 0, 0);
    float4 bv0 = *(const float4*)(Bp + (size_t)br * DMODEL + bc);
    float4 bv1 = *(const float4*)(Bp + (size_t)br * DMODEL + bc + 64);

    As[0][ac + 0][ar] = av.x; As[0][ac + 1][ar] = av.y;
    As[0][ac + 2][ar] = av.z; As[0][ac + 3][ar] = av.w;
    *(float4*)&Bs[0][br][bc]      = bv0;
    *(float4*)&Bs[0][br][bc + 64] = bv1;
    __syncthreads();

    int ty = tid >> 4, tx = tid & 15;
    int trow = ty * 4, tc = tx * 4;
    float acc[4][8] = {};

    const int NT_ = K / BK;
    for (int t = 0; t < NT_; t++) {
        int buf = t & 1;
        int kn  = (t + 1) * BK;
        if (kn < K) {
            if (aok) av = *(const float4*)(Arow + kn + ac);
            bv0 = *(const float4*)(Bp + (size_t)(kn + br) * DMODEL + bc);
            bv1 = *(const float4*)(Bp + (size_t)(kn + br) * DMODEL + bc + 64);
        }
#pragma unroll
        for (int k = 0; k < BK; k++) {
            float4 a  = *(const float4*)&As[buf][k][trow];
            float4 b0 = *(const float4*)&Bs[buf][k][tc];
            float4 b1 = *(const float4*)&Bs[buf][k][tc + 64];
            float aa[4] = { a.x, a.y, a.z, a.w };
            float bb[8] = { b0.x, b0.y, b0.z, b0.w, b1.x, b1.y, b1.z, b1.w };
#pragma unroll
            for (int i = 0; i < 4; i++)
#pragma unroll
                for (int j = 0; j < 8; j++)
                    acc[i][j] = fmaf(aa[i], bb[j], acc[i][j]);
        }
        if (kn < K) {
            int nb = buf ^ 1;
            As[nb][ac + 0][ar] = av.x; As[nb][ac + 1][ar] = av.y;
            As[nb][ac + 2][ar] = av.z; As[nb][ac + 3][ar] = av.w;
            *(float4*)&Bs[nb][br][bc]      = bv0;
            *(float4*)&Bs[nb][br][bc + 64] = bv1;
        }
        __syncthreads();
    }

#pragma unroll
    for (int i = 0; i < 4; i++) {
        int r = trow + i;
        if (m0 + r < ne) {
            int   tk = stok[r];
            float w  = sgate[r];
            float* op = out + (size_t)tk * DMODEL + n0;
#pragma unroll
            for (int j = 0; j < 4; j++) {
                atomicAdd(op + tc + j,      w * acc[i][j]);
                atomicAdd(op + tc + 64 + j, w * acc[i][j + 4]);
            }
        }
    }
}

// ---------------- launch -----------------------------------------------------
extern "C" void kernel_launch(void* const* d_in, const int* in_sizes, int n_in,
                              void* d_out, int out_size) {
    const float* x   = (const float*)d_in[0];
    const float* Wg  = (const float*)d_in[1];
    const float* W1  = (const float*)d_in[2];
    const float* W3  = (const float*)d_in[3];
    const float* W2  = (const float*)d_in[4];
    const float* Ws1 = (const float*)d_in[5];
    const float* Ws3 = (const float*)d_in[6];
    const float* Ws2 = (const float*)d_in[7];
    float* out = (float*)d_out;

    cudaMemsetAsync(out, 0, (size_t)NTOK * DMODEL * sizeof(float));
    zero_kernel<<<1, 32>>>();
    router_kernel<<<NTOK / 8, 256>>>(x, Wg);
    scanfill_kernel<<<1, 1024>>>();

    // fused up-proj: routed (z=0..7) + shared halves (z=8,9)
    gemm1_all<<<dim3(HEXP / 64, NTOK / 64, 10), 128>>>(x, W1, W3, Ws1, Ws3);
    // fused down-proj: routed (z=0..7) + shared (z=8), all atomic into out
    gemm2_all<<<dim3(DMODEL / 128, NTOK / 64, 9), 256>>>(W2, Ws2, out);
}

// round 14
// speedup vs baseline: 1.1413x; 1.1413x over previous
#include <cuda_runtime.h>
#include <cstdint>

#define NTOK   4096
#define DMODEL 1024
#define NEXP   8
#define TOPK   2
#define HEXP   704
#define HSH    1408
#define BK     16

// ---------------- scratch (device globals; no allocation allowed) ----------
__device__ int   g_cnt[NEXP];
__device__ int   g_off[NEXP + 1];
__device__ int   g_topi[NTOK * TOPK];
__device__ float g_topw[NTOK * TOPK];
__device__ int   g_tok[NTOK * TOPK];
__device__ float g_gate[NTOK * TOPK];
__device__ float g_hid_r[NTOK * TOPK * HEXP];   // routed SwiGLU hidden
__device__ float g_hid_s[NTOK * HSH];           // shared-expert hidden

// ---------------- cp.async helpers ------------------------------------------
__device__ __forceinline__ void cp16(void* dst, const void* src) {
    uint32_t s = (uint32_t)__cvta_generic_to_shared(dst);
    asm volatile("cp.async.cg.shared.global [%0], [%1], 16;"
                 :: "r"(s), "l"(src) : "memory");
}
#define CP_COMMIT() asm volatile("cp.async.commit_group;" ::: "memory")
#define CP_WAIT0()  asm volatile("cp.async.wait_group 0;" ::: "memory")

// ---------------- setup kernels ---------------------------------------------
__global__ void zero_kernel() {
    int t = threadIdx.x;
    if (t < NEXP) g_cnt[t] = 0;
}

__global__ void router_kernel(const float* __restrict__ x,
                              const float* __restrict__ Wg) {
    int gw   = (blockIdx.x * blockDim.x + threadIdx.x) >> 5;
    int lane = threadIdx.x & 31;
    if (gw >= NTOK) return;
    const float* xr = x + (size_t)gw * DMODEL;

    float acc[NEXP];
#pragma unroll
    for (int e = 0; e < NEXP; e++) acc[e] = 0.f;
    for (int k = lane; k < DMODEL; k += 32) {
        float xv = xr[k];
#pragma unroll
        for (int e = 0; e < NEXP; e++) acc[e] += xv * Wg[e * DMODEL + k];
    }
#pragma unroll
    for (int e = 0; e < NEXP; e++) {
#pragma unroll
        for (int o = 16; o > 0; o >>= 1)
            acc[e] += __shfl_xor_sync(0xffffffffu, acc[e], o);
    }
    if (lane == 0) {
        float m = acc[0];
#pragma unroll
        for (int e = 1; e < NEXP; e++) m = fmaxf(m, acc[e]);
        float p[NEXP], s = 0.f;
#pragma unroll
        for (int e = 0; e < NEXP; e++) { p[e] = expf(acc[e] - m); s += p[e]; }
        float inv = 1.f / s;
#pragma unroll
        for (int e = 0; e < NEXP; e++) p[e] *= inv;

        int i0 = 0; float v0 = p[0];
#pragma unroll
        for (int e = 1; e < NEXP; e++) if (p[e] > v0) { v0 = p[e]; i0 = e; }
        int i1 = (i0 == 0) ? 1 : 0; float v1 = p[i1];
#pragma unroll
        for (int e = 0; e < NEXP; e++)
            if (e != i0 && p[e] > v1) { v1 = p[e]; i1 = e; }

        float sw = v0 + v1 + 1e-20f;
        g_topi[gw * 2] = i0;  g_topi[gw * 2 + 1] = i1;
        g_topw[gw * 2] = v0 / sw;  g_topw[gw * 2 + 1] = v1 / sw;
        atomicAdd(&g_cnt[i0], 1);
        atomicAdd(&g_cnt[i1], 1);
    }
}

// single block: exclusive scan of g_cnt, then scatter fill
__global__ void scanfill_kernel() {
    __shared__ int s_off[NEXP + 1];
    __shared__ int s_cur[NEXP];
    int tid = threadIdx.x;
    if (tid == 0) {
        int acc = 0;
        s_off[0] = 0;
        for (int e = 0; e < NEXP; e++) {
            acc += g_cnt[e];
            s_off[e + 1] = acc;
            s_cur[e] = 0;
        }
        for (int e = 0; e <= NEXP; e++) g_off[e] = s_off[e];
    }
    __syncthreads();
    for (int n = tid; n < NTOK; n += blockDim.x) {
#pragma unroll
        for (int s = 0; s < TOPK; s++) {
            int e   = g_topi[n * 2 + s];
            int pos = atomicAdd(&s_cur[e], 1);
            int idx = s_off[e] + pos;
            g_tok[idx]  = n;
            g_gate[idx] = g_topw[n * 2 + s];
        }
    }
}

__device__ __forceinline__ float silu_f(float z) {
    return z / (1.f + __expf(-z));
}

// ============ GEMM1 fused: hid = silu(A@W1)*(A@W3) ==========================
// grid (11, 32, 10). CTA 128x64, 256 thr = 32(ty)x8(tx), tile 4x(8+8).
// A: reg-prefetch + STS transpose. B: cp.async (no prefetch regs, L1 bypass).
__global__ __launch_bounds__(256, 2)
void gemm1_all(const float* __restrict__ x,
               const float* __restrict__ W1,
               const float* __restrict__ W3,
               const float* __restrict__ Ws1,
               const float* __restrict__ Ws3) {
    int z = blockIdx.z;
    bool routed = (z < NEXP);
    int base = 0, ne = NTOK, H, n0;
    const float *B1, *B3;
    float* hid;
    if (routed) {
        base = g_off[z]; ne = g_off[z + 1] - base;
        H = HEXP; hid = g_hid_r;
        n0 = blockIdx.x * 64;
        B1 = W1 + (size_t)z * DMODEL * HEXP + n0;
        B3 = W3 + (size_t)z * DMODEL * HEXP + n0;
    } else {
        H = HSH; hid = g_hid_s;
        n0 = (blockIdx.x + (z - NEXP) * 11) * 64;
        B1 = Ws1 + n0;
        B3 = Ws3 + n0;
    }
    int m0 = blockIdx.y * 128;
    if (m0 >= ne) return;

    __shared__ float As[2][BK][132];
    __shared__ float Bs1[2][BK][64];
    __shared__ float Bs3[2][BK][64];
    __shared__ int   stok[128];

    int tid = threadIdx.x;
    if (tid < 128)
        stok[tid] = routed ? ((m0 + tid < ne) ? g_tok[base + m0 + tid] : -1)
                           : (m0 + tid);
    __syncthreads();

    // A loader: row = tid>>1, k-octet = (tid&1)*8
    int ar = tid >> 1, ac = (tid & 1) * 8;
    int tk = stok[ar];
    bool aok = (tk >= 0);
    const float* Arow = x + (size_t)(aok ? tk : 0) * DMODEL;
    // B loader: k = tid>>4, chunk = (tid&15)*4 (one 16B chunk per matrix)
    int br = tid >> 4, bc = (tid & 15) * 4;

    float4 av0 = make_float4(0, 0, 0, 0), av1 = make_float4(0, 0, 0, 0);
    if (aok) {
        av0 = *(const float4*)(Arow + ac);
        av1 = *(const float4*)(Arow + ac + 4);
    }
    // prologue: stage tile 0 into buffer 0
    As[0][ac + 0][ar] = av0.x; As[0][ac + 1][ar] = av0.y;
    As[0][ac + 2][ar] = av0.z; As[0][ac + 3][ar] = av0.w;
    As[0][ac + 4][ar] = av1.x; As[0][ac + 5][ar] = av1.y;
    As[0][ac + 6][ar] = av1.z; As[0][ac + 7][ar] = av1.w;
    cp16(&Bs1[0][br][bc], B1 + (size_t)br * H + bc);
    cp16(&Bs3[0][br][bc], B3 + (size_t)br * H + bc);
    CP_COMMIT();
    CP_WAIT0();
    __syncthreads();

    int ty = tid >> 3, tx = tid & 7;
    int trow = ty * 4, tc = tx * 4;
    float acc1[4][8] = {}, acc3[4][8] = {};

    const int NT = DMODEL / BK;
    for (int t = 0; t < NT; t++) {
        int buf = t & 1, nb = buf ^ 1;
        int kn  = (t + 1) * BK;
        if (kn < DMODEL) {
            if (aok) {
                av0 = *(const float4*)(Arow + kn + ac);
                av1 = *(const float4*)(Arow + kn + ac + 4);
            }
            cp16(&Bs1[nb][br][bc], B1 + (size_t)(kn + br) * H + bc);
            cp16(&Bs3[nb][br][bc], B3 + (size_t)(kn + br) * H + bc);
            CP_COMMIT();
        }
#pragma unroll
        for (int k = 0; k < BK; k++) {
            float4 a  = *(const float4*)&As[buf][k][trow];
            float4 p0 = *(const float4*)&Bs1[buf][k][tc];
            float4 p1 = *(const float4*)&Bs1[buf][k][tc + 32];
            float4 q0 = *(const float4*)&Bs3[buf][k][tc];
            float4 q1 = *(const float4*)&Bs3[buf][k][tc + 32];
            float aa[4] = { a.x, a.y, a.z, a.w };
            float pp[8] = { p0.x, p0.y, p0.z, p0.w, p1.x, p1.y, p1.z, p1.w };
            float qq[8] = { q0.x, q0.y, q0.z, q0.w, q1.x, q1.y, q1.z, q1.w };
#pragma unroll
            for (int i = 0; i < 4; i++)
#pragma unroll
                for (int j = 0; j < 8; j++) {
                    acc1[i][j] = fmaf(aa[i], pp[j], acc1[i][j]);
                    acc3[i][j] = fmaf(aa[i], qq[j], acc3[i][j]);
                }
        }
        if (kn < DMODEL) {
            As[nb][ac + 0][ar] = av0.x; As[nb][ac + 1][ar] = av0.y;
            As[nb][ac + 2][ar] = av0.z; As[nb][ac + 3][ar] = av0.w;
            As[nb][ac + 4][ar] = av1.x; As[nb][ac + 5][ar] = av1.y;
            As[nb][ac + 6][ar] = av1.z; As[nb][ac + 7][ar] = av1.w;
            CP_WAIT0();
        }
        __syncthreads();
    }

#pragma unroll
    for (int i = 0; i < 4; i++) {
        int r = trow + i;
        if (m0 + r < ne) {
            size_t rowoff = (size_t)(base + m0 + r) * H + n0;
            float4 h0, h1;
            h0.x = silu_f(acc1[i][0]) * acc3[i][0];
            h0.y = silu_f(acc1[i][1]) * acc3[i][1];
            h0.z = silu_f(acc1[i][2]) * acc3[i][2];
            h0.w = silu_f(acc1[i][3]) * acc3[i][3];
            h1.x = silu_f(acc1[i][4]) * acc3[i][4];
            h1.y = silu_f(acc1[i][5]) * acc3[i][5];
            h1.z = silu_f(acc1[i][6]) * acc3[i][6];
            h1.w = silu_f(acc1[i][7]) * acc3[i][7];
            *(float4*)&hid[rowoff + tc]      = h0;
            *(float4*)&hid[rowoff + tc + 32] = h1;
        }
    }
}

// ============ GEMM2 fused: out += w * (hid @ W2) ============================
// grid (8, 32, 9). CTA 128x128, 256 thr = 32(ty)x8(tx), tile 4x16 (4 col-quads).
// A: reg-prefetch + STS transpose. B: cp.async. out pre-zeroed, atomicAdd.
__global__ __launch_bounds__(256, 2)
void gemm2_all(const float* __restrict__ W2,
               const float* __restrict__ Ws2,
               float* __restrict__ out) {
    int z = blockIdx.z;
    bool routed = (z < NEXP);
    int base = 0, ne = NTOK, K;
    const float* Bp;
    const float* hidg;
    int n0 = blockIdx.x * 128;
    if (routed) {
        base = g_off[z]; ne = g_off[z + 1] - base;
        K = HEXP; hidg = g_hid_r;
        Bp = W2 + (size_t)z * HEXP * DMODEL + n0;
    } else {
        K = HSH; hidg = g_hid_s;
        Bp = Ws2 + n0;
    }
    int m0 = blockIdx.y * 128;
    if (m0 >= ne) return;

    __shared__ float As[2][BK][132];
    __shared__ float Bs[2][BK][128];
    __shared__ int   stok[128];
    __shared__ float sgate[128];

    int tid = threadIdx.x;
    if (tid < 128) {
        if (routed) {
            bool v = (m0 + tid < ne);
            stok[tid]  = v ? g_tok[base + m0 + tid] : 0;
            sgate[tid] = v ? g_gate[base + m0 + tid] : 0.f;
        } else {
            stok[tid]  = m0 + tid;
            sgate[tid] = 1.f;
        }
    }
    __syncthreads();

    int ar = tid >> 1, ac = (tid & 1) * 8;
    bool aok = (m0 + ar < ne);
    const float* Arow = hidg + (size_t)(base + m0 + (aok ? ar : 0)) * K;
    // B loader: k = tid>>4, two 16B chunks at bc and bc+64
    int br = tid >> 4, bc = (tid & 15) * 4;

    float4 av0 = make_float4(0, 0, 0, 0), av1 = make_float4(0, 0, 0, 0);
    if (aok) {
        av0 = *(const float4*)(Arow + ac);
        av1 = *(const float4*)(Arow + ac + 4);
    }
    As[0][ac + 0][ar] = av0.x; As[0][ac + 1][ar] = av0.y;
    As[0][ac + 2][ar] = av0.z; As[0][ac + 3][ar] = av0.w;
    As[0][ac + 4][ar] = av1.x; As[0][ac + 5][ar] = av1.y;
    As[0][ac + 6][ar] = av1.z; As[0][ac + 7][ar] = av1.w;
    cp16(&Bs[0][br][bc],      Bp + (size_t)br * DMODEL + bc);
    cp16(&Bs[0][br][bc + 64], Bp + (size_t)br * DMODEL + bc + 64);
    CP_COMMIT();
    CP_WAIT0();
    __syncthreads();

    int ty = tid >> 3, tx = tid & 7;
    int trow = ty * 4, tc = tx * 4;
    float acc[4][16] = {};

    const int NT_ = K / BK;
    for (int t = 0; t < NT_; t++) {
        int buf = t & 1, nb = buf ^ 1;
        int kn  = (t + 1) * BK;
        if (kn < K) {
            if (aok) {
                av0 = *(const float4*)(Arow + kn + ac);
                av1 = *(const float4*)(Arow + kn + ac + 4);
            }
            cp16(&Bs[nb][br][bc],      Bp + (size_t)(kn + br) * DMODEL + bc);
            cp16(&Bs[nb][br][bc + 64], Bp + (size_t)(kn + br) * DMODEL + bc + 64);
            CP_COMMIT();
        }
#pragma unroll
        for (int k = 0; k < BK; k++) {
            float4 a  = *(const float4*)&As[buf][k][trow];
            float4 b0 = *(const float4*)&Bs[buf][k][tc];
            float4 b1 = *(const float4*)&Bs[buf][k][tc + 32];
            float4 b2 = *(const float4*)&Bs[buf][k][tc + 64];
            float4 b3 = *(const float4*)&Bs[buf][k][tc + 96];
            float aa[4]  = { a.x, a.y, a.z, a.w };
            float bb[16] = { b0.x, b0.y, b0.z, b0.w, b1.x, b1.y, b1.z, b1.w,
                             b2.x, b2.y, b2.z, b2.w, b3.x, b3.y, b3.z, b3.w };
#pragma unroll
            for (int i = 0; i < 4; i++)
#pragma unroll
                for (int j = 0; j < 16; j++)
                    acc[i][j] = fmaf(aa[i], bb[j], acc[i][j]);
        }
        if (kn < K) {
            As[nb][ac + 0][ar] = av0.x; As[nb][ac + 1][ar] = av0.y;
            As[nb][ac + 2][ar] = av0.z; As[nb][ac + 3][ar] = av0.w;
            As[nb][ac + 4][ar] = av1.x; As[nb][ac + 5][ar] = av1.y;
            As[nb][ac + 6][ar] = av1.z; As[nb][ac + 7][ar] = av1.w;
            CP_WAIT0();
        }
        __syncthreads();
    }

#pragma unroll
    for (int i = 0; i < 4; i++) {
        int r = trow + i;
        if (m0 + r < ne) {
            int   tk = stok[r];
            float w  = sgate[r];
            float* op = out + (size_t)tk * DMODEL + n0;
#pragma unroll
            for (int g = 0; g < 4; g++) {
                int col = tc + g * 32;
#pragma unroll
                for (int j = 0; j < 4; j++)
                    atomicAdd(op + col + j, w * acc[i][g * 4 + j]);
            }
        }
    }
}

// ---------------- launch -----------------------------------------------------
extern "C" void kernel_launch(void* const* d_in, const int* in_sizes, int n_in,
                              void* d_out, int out_size) {
    const float* x   = (const float*)d_in[0];
    const float* Wg  = (const float*)d_in[1];
    const float* W1  = (const float*)d_in[2];
    const float* W3  = (const float*)d_in[3];
    const float* W2  = (const float*)d_in[4];
    const float* Ws1 = (const float*)d_in[5];
    const float* Ws3 = (const float*)d_in[6];
    const float* Ws2 = (const float*)d_in[7];
    float* out = (float*)d_out;

    cudaMemsetAsync(out, 0, (size_t)NTOK * DMODEL * sizeof(float));
    zero_kernel<<<1, 32>>>();
    router_kernel<<<NTOK / 8, 256>>>(x, Wg);
    scanfill_kernel<<<1, 1024>>>();

    // fused up-proj: routed (z=0..7) + shared halves (z=8,9)
    gemm1_all<<<dim3(HEXP / 64, NTOK / 128, 10), 256>>>(x, W1, W3, Ws1, Ws3);
    // fused down-proj: routed (z=0..7) + shared (z=8), all atomic into out
    gemm2_all<<<dim3(DMODEL / 128, NTOK / 128, 9), 256>>>(W2, Ws2, out);
}

// round 15
// speedup vs baseline: 1.1745x; 1.0292x over previous
#include <cuda_runtime.h>
#include <cstdint>

#define NTOK   4096
#define DMODEL 1024
#define NEXP   8
#define TOPK   2
#define HEXP   704
#define HSH    1408
#define BK     16

// ---------------- scratch (device globals; no allocation allowed) ----------
__device__ int   g_cnt[NEXP];
__device__ int   g_off[NEXP + 1];
__device__ int   g_topi[NTOK * TOPK];
__device__ float g_topw[NTOK * TOPK];
__device__ int   g_tok[NTOK * TOPK];
__device__ float g_gate[NTOK * TOPK];
__device__ float g_hid_r[NTOK * TOPK * HEXP];   // routed SwiGLU hidden
__device__ float g_hid_s[NTOK * HSH];           // shared-expert hidden

// ---------------- cp.async helpers ------------------------------------------
__device__ __forceinline__ void cp16(void* dst, const void* src) {
    uint32_t s = (uint32_t)__cvta_generic_to_shared(dst);
    asm volatile("cp.async.cg.shared.global [%0], [%1], 16;"
                 :: "r"(s), "l"(src) : "memory");
}
#define CP_COMMIT() asm volatile("cp.async.commit_group;" ::: "memory")
#define CP_WAIT0()  asm volatile("cp.async.wait_group 0;" ::: "memory")

// ---------------- setup kernels ---------------------------------------------
__global__ void zero_kernel() {
    int t = threadIdx.x;
    if (t < NEXP) g_cnt[t] = 0;
}

__global__ void router_kernel(const float* __restrict__ x,
                              const float* __restrict__ Wg) {
    int gw   = (blockIdx.x * blockDim.x + threadIdx.x) >> 5;
    int lane = threadIdx.x & 31;
    if (gw >= NTOK) return;
    const float* xr = x + (size_t)gw * DMODEL;

    float acc[NEXP];
#pragma unroll
    for (int e = 0; e < NEXP; e++) acc[e] = 0.f;
    for (int k = lane; k < DMODEL; k += 32) {
        float xv = xr[k];
#pragma unroll
        for (int e = 0; e < NEXP; e++) acc[e] += xv * Wg[e * DMODEL + k];
    }
#pragma unroll
    for (int e = 0; e < NEXP; e++) {
#pragma unroll
        for (int o = 16; o > 0; o >>= 1)
            acc[e] += __shfl_xor_sync(0xffffffffu, acc[e], o);
    }
    if (lane == 0) {
        float m = acc[0];
#pragma unroll
        for (int e = 1; e < NEXP; e++) m = fmaxf(m, acc[e]);
        float p[NEXP], s = 0.f;
#pragma unroll
        for (int e = 0; e < NEXP; e++) { p[e] = expf(acc[e] - m); s += p[e]; }
        float inv = 1.f / s;
#pragma unroll
        for (int e = 0; e < NEXP; e++) p[e] *= inv;

        int i0 = 0; float v0 = p[0];
#pragma unroll
        for (int e = 1; e < NEXP; e++) if (p[e] > v0) { v0 = p[e]; i0 = e; }
        int i1 = (i0 == 0) ? 1 : 0; float v1 = p[i1];
#pragma unroll
        for (int e = 0; e < NEXP; e++)
            if (e != i0 && p[e] > v1) { v1 = p[e]; i1 = e; }

        float sw = v0 + v1 + 1e-20f;
        g_topi[gw * 2] = i0;  g_topi[gw * 2 + 1] = i1;
        g_topw[gw * 2] = v0 / sw;  g_topw[gw * 2 + 1] = v1 / sw;
        atomicAdd(&g_cnt[i0], 1);
        atomicAdd(&g_cnt[i1], 1);
    }
}

// single block: exclusive scan of g_cnt, then scatter fill
__global__ void scanfill_kernel() {
    __shared__ int s_off[NEXP + 1];
    __shared__ int s_cur[NEXP];
    int tid = threadIdx.x;
    if (tid == 0) {
        int acc = 0;
        s_off[0] = 0;
        for (int e = 0; e < NEXP; e++) {
            acc += g_cnt[e];
            s_off[e + 1] = acc;
            s_cur[e] = 0;
        }
        for (int e = 0; e <= NEXP; e++) g_off[e] = s_off[e];
    }
    __syncthreads();
    for (int n = tid; n < NTOK; n += blockDim.x) {
#pragma unroll
        for (int s = 0; s < TOPK; s++) {
            int e   = g_topi[n * 2 + s];
            int pos = atomicAdd(&s_cur[e], 1);
            int idx = s_off[e] + pos;
            g_tok[idx]  = n;
            g_gate[idx] = g_topw[n * 2 + s];
        }
    }
}

__device__ __forceinline__ float silu_f(float z) {
    return z / (1.f + __expf(-z));
}

// ============ GEMM1 fused: hid = silu(A@W1)*(A@W3) ==========================
// grid (11, 32, 10). CTA 128x64, 256 thr; thread tile 8 rows x 4 cols/matrix
// (trow=(tid>>4)*8, tc=(tid&15)*4: 16 distinct B-chunks per lane group ->
// no phase duplication on the smem crossbar). A: reg-prefetch+STS; B: cp.async.
__global__ __launch_bounds__(256, 2)
void gemm1_all(const float* __restrict__ x,
               const float* __restrict__ W1,
               const float* __restrict__ W3,
               const float* __restrict__ Ws1,
               const float* __restrict__ Ws3) {
    int z = blockIdx.z;
    bool routed = (z < NEXP);
    int base = 0, ne = NTOK, H, n0;
    const float *B1, *B3;
    float* hid;
    if (routed) {
        base = g_off[z]; ne = g_off[z + 1] - base;
        H = HEXP; hid = g_hid_r;
        n0 = blockIdx.x * 64;
        B1 = W1 + (size_t)z * DMODEL * HEXP + n0;
        B3 = W3 + (size_t)z * DMODEL * HEXP + n0;
    } else {
        H = HSH; hid = g_hid_s;
        n0 = (blockIdx.x + (z - NEXP) * 11) * 64;
        B1 = Ws1 + n0;
        B3 = Ws3 + n0;
    }
    int m0 = blockIdx.y * 128;
    if (m0 >= ne) return;

    __shared__ float As[2][BK][132];
    __shared__ float Bs1[2][BK][64];
    __shared__ float Bs3[2][BK][64];
    __shared__ int   stok[128];

    int tid = threadIdx.x;
    if (tid < 128)
        stok[tid] = routed ? ((m0 + tid < ne) ? g_tok[base + m0 + tid] : -1)
                           : (m0 + tid);
    __syncthreads();

    // A loader: row = tid>>1, k-octet = (tid&1)*8
    int ar = tid >> 1, ac = (tid & 1) * 8;
    int tk = stok[ar];
    bool aok = (tk >= 0);
    const float* Arow = x + (size_t)(aok ? tk : 0) * DMODEL;
    // B loader: k = tid>>4, chunk = (tid&15)*4 (one 16B chunk per matrix)
    int br = tid >> 4, bc = (tid & 15) * 4;

    float4 av0 = make_float4(0, 0, 0, 0), av1 = make_float4(0, 0, 0, 0);
    if (aok) {
        av0 = *(const float4*)(Arow + ac);
        av1 = *(const float4*)(Arow + ac + 4);
    }
    As[0][ac + 0][ar] = av0.x; As[0][ac + 1][ar] = av0.y;
    As[0][ac + 2][ar] = av0.z; As[0][ac + 3][ar] = av0.w;
    As[0][ac + 4][ar] = av1.x; As[0][ac + 5][ar] = av1.y;
    As[0][ac + 6][ar] = av1.z; As[0][ac + 7][ar] = av1.w;
    cp16(&Bs1[0][br][bc], B1 + (size_t)br * H + bc);
    cp16(&Bs3[0][br][bc], B3 + (size_t)br * H + bc);
    CP_COMMIT();
    CP_WAIT0();
    __syncthreads();

    int trow = (tid >> 4) * 8, tc = (tid & 15) * 4;
    float acc1[8][4] = {}, acc3[8][4] = {};

    const int NT = DMODEL / BK;
    for (int t = 0; t < NT; t++) {
        int buf = t & 1, nb = buf ^ 1;
        int kn  = (t + 1) * BK;
        if (kn < DMODEL) {
            if (aok) {
                av0 = *(const float4*)(Arow + kn + ac);
                av1 = *(const float4*)(Arow + kn + ac + 4);
            }
            cp16(&Bs1[nb][br][bc], B1 + (size_t)(kn + br) * H + bc);
            cp16(&Bs3[nb][br][bc], B3 + (size_t)(kn + br) * H + bc);
            CP_COMMIT();
        }
#pragma unroll
        for (int k = 0; k < BK; k++) {
            float4 a0 = *(const float4*)&As[buf][k][trow];
            float4 a1 = *(const float4*)&As[buf][k][trow + 4];
            float4 p  = *(const float4*)&Bs1[buf][k][tc];
            float4 q  = *(const float4*)&Bs3[buf][k][tc];
            float aa[8] = { a0.x, a0.y, a0.z, a0.w, a1.x, a1.y, a1.z, a1.w };
            float pp[4] = { p.x, p.y, p.z, p.w };
            float qq[4] = { q.x, q.y, q.z, q.w };
#pragma unroll
            for (int i = 0; i < 8; i++)
#pragma unroll
                for (int j = 0; j < 4; j++) {
                    acc1[i][j] = fmaf(aa[i], pp[j], acc1[i][j]);
                    acc3[i][j] = fmaf(aa[i], qq[j], acc3[i][j]);
                }
        }
        if (kn < DMODEL) {
            As[nb][ac + 0][ar] = av0.x; As[nb][ac + 1][ar] = av0.y;
            As[nb][ac + 2][ar] = av0.z; As[nb][ac + 3][ar] = av0.w;
            As[nb][ac + 4][ar] = av1.x; As[nb][ac + 5][ar] = av1.y;
            As[nb][ac + 6][ar] = av1.z; As[nb][ac + 7][ar] = av1.w;
            CP_WAIT0();
        }
        __syncthreads();
    }

#pragma unroll
    for (int i = 0; i < 8; i++) {
        int r = trow + i;
        if (m0 + r < ne) {
            float4 hv;
            hv.x = silu_f(acc1[i][0]) * acc3[i][0];
            hv.y = silu_f(acc1[i][1]) * acc3[i][1];
            hv.z = silu_f(acc1[i][2]) * acc3[i][2];
            hv.w = silu_f(acc1[i][3]) * acc3[i][3];
            *(float4*)&hid[(size_t)(base + m0 + r) * H + n0 + tc] = hv;
        }
    }
}

// ============ GEMM2 fused: out += w * (hid @ W2) ============================
// grid (8, 32, 9). CTA 128x128, 256 thr; thread tile 8 rows x (4+4) cols
// (tc and tc+64). A: reg-prefetch+STS; B: cp.async. out pre-zeroed, atomicAdd.
__global__ __launch_bounds__(256, 2)
void gemm2_all(const float* __restrict__ W2,
               const float* __restrict__ Ws2,
               float* __restrict__ out) {
    int z = blockIdx.z;
    bool routed = (z < NEXP);
    int base = 0, ne = NTOK, K;
    const float* Bp;
    const float* hidg;
    int n0 = blockIdx.x * 128;
    if (routed) {
        base = g_off[z]; ne = g_off[z + 1] - base;
        K = HEXP; hidg = g_hid_r;
        Bp = W2 + (size_t)z * HEXP * DMODEL + n0;
    } else {
        K = HSH; hidg = g_hid_s;
        Bp = Ws2 + n0;
    }
    int m0 = blockIdx.y * 128;
    if (m0 >= ne) return;

    __shared__ float As[2][BK][132];
    __shared__ float Bs[2][BK][128];
    __shared__ int   stok[128];
    __shared__ float sgate[128];

    int tid = threadIdx.x;
    if (tid < 128) {
        if (routed) {
            bool v = (m0 + tid < ne);
            stok[tid]  = v ? g_tok[base + m0 + tid] : 0;
            sgate[tid] = v ? g_gate[base + m0 + tid] : 0.f;
        } else {
            stok[tid]  = m0 + tid;
            sgate[tid] = 1.f;
        }
    }
    __syncthreads();

    int ar = tid >> 1, ac = (tid & 1) * 8;
    bool aok = (m0 + ar < ne);
    const float* Arow = hidg + (size_t)(base + m0 + (aok ? ar : 0)) * K;
    int br = tid >> 4, bc = (tid & 15) * 4;

    float4 av0 = make_float4(0, 0, 0, 0), av1 = make_float4(0, 0, 0, 0);
    if (aok) {
        av0 = *(const float4*)(Arow + ac);
        av1 = *(const float4*)(Arow + ac + 4);
    }
    As[0][ac + 0][ar] = av0.x; As[0][ac + 1][ar] = av0.y;
    As[0][ac + 2][ar] = av0.z; As[0][ac + 3][ar] = av0.w;
    As[0][ac + 4][ar] = av1.x; As[0][ac + 5][ar] = av1.y;
    As[0][ac + 6][ar] = av1.z; As[0][ac + 7][ar] = av1.w;
    cp16(&Bs[0][br][bc],      Bp + (size_t)br * DMODEL + bc);
    cp16(&Bs[0][br][bc + 64], Bp + (size_t)br * DMODEL + bc + 64);
    CP_COMMIT();
    CP_WAIT0();
    __syncthreads();

    int trow = (tid >> 4) * 8, tc = (tid & 15) * 4;
    float acc[8][8] = {};

    const int NT_ = K / BK;
    for (int t = 0; t < NT_; t++) {
        int buf = t & 1, nb = buf ^ 1;
        int kn  = (t + 1) * BK;
        if (kn < K) {
            if (aok) {
                av0 = *(const float4*)(Arow + kn + ac);
                av1 = *(const float4*)(Arow + kn + ac + 4);
            }
            cp16(&Bs[nb][br][bc],      Bp + (size_t)(kn + br) * DMODEL + bc);
            cp16(&Bs[nb][br][bc + 64], Bp + (size_t)(kn + br) * DMODEL + bc + 64);
            CP_COMMIT();
        }
#pragma unroll
        for (int k = 0; k < BK; k++) {
            float4 a0 = *(const float4*)&As[buf][k][trow];
            float4 a1 = *(const float4*)&As[buf][k][trow + 4];
            float4 b0 = *(const float4*)&Bs[buf][k][tc];
            float4 b1 = *(const float4*)&Bs[buf][k][tc + 64];
            float aa[8] = { a0.x, a0.y, a0.z, a0.w, a1.x, a1.y, a1.z, a1.w };
            float bb[8] = { b0.x, b0.y, b0.z, b0.w, b1.x, b1.y, b1.z, b1.w };
#pragma unroll
            for (int i = 0; i < 8; i++)
#pragma unroll
                for (int j = 0; j < 8; j++)
                    acc[i][j] = fmaf(aa[i], bb[j], acc[i][j]);
        }
        if (kn < K) {
            As[nb][ac + 0][ar] = av0.x; As[nb][ac + 1][ar] = av0.y;
            As[nb][ac + 2][ar] = av0.z; As[nb][ac + 3][ar] = av0.w;
            As[nb][ac + 4][ar] = av1.x; As[nb][ac + 5][ar] = av1.y;
            As[nb][ac + 6][ar] = av1.z; As[nb][ac + 7][ar] = av1.w;
            CP_WAIT0();
        }
        __syncthreads();
    }

#pragma unroll
    for (int i = 0; i < 8; i++) {
        int r = trow + i;
        if (m0 + r < ne) {
            int   tk = stok[r];
            float w  = sgate[r];
            float* op = out + (size_t)tk * DMODEL + n0;
#pragma unroll
            for (int j = 0; j < 4; j++) {
                atomicAdd(op + tc + j,      w * acc[i][j]);
                atomicAdd(op + tc + 64 + j, w * acc[i][j + 4]);
            }
        }
    }
}

// ---------------- launch -----------------------------------------------------
extern "C" void kernel_launch(void* const* d_in, const int* in_sizes, int n_in,
                              void* d_out, int out_size) {
    const float* x   = (const float*)d_in[0];
    const float* Wg  = (const float*)d_in[1];
    const float* W1  = (const float*)d_in[2];
    const float* W3  = (const float*)d_in[3];
    const float* W2  = (const float*)d_in[4];
    const float* Ws1 = (const float*)d_in[5];
    const float* Ws3 = (const float*)d_in[6];
    const float* Ws2 = (const float*)d_in[7];
    float* out = (float*)d_out;

    cudaMemsetAsync(out, 0, (size_t)NTOK * DMODEL * sizeof(float));
    zero_kernel<<<1, 32>>>();
    router_kernel<<<NTOK / 8, 256>>>(x, Wg);
    scanfill_kernel<<<1, 1024>>>();

    // fused up-proj: routed (z=0..7) + shared halves (z=8,9)
    gemm1_all<<<dim3(HEXP / 64, NTOK / 128, 10), 256>>>(x, W1, W3, Ws1, Ws3);
    // fused down-proj: routed (z=0..7) + shared (z=8), all atomic into out
    gemm2_all<<<dim3(DMODEL / 128, NTOK / 128, 9), 256>>>(W2, Ws2, out);
}

// round 16
// speedup vs baseline: 1.1964x; 1.0186x over previous
#include <cuda_runtime.h>
#include <cstdint>

#define NTOK   4096
#define DMODEL 1024
#define NEXP   8
#define TOPK   2
#define HEXP   704
#define HSH    1408
#define BK     32

// ---------------- scratch (device globals; no allocation allowed) ----------
__device__ int   g_cnt[NEXP];
__device__ int   g_off[NEXP + 1];
__device__ int   g_topi[NTOK * TOPK];
__device__ float g_topw[NTOK * TOPK];
__device__ int   g_tok[NTOK * TOPK];
__device__ float g_gate[NTOK * TOPK];
__device__ float g_hid_r[NTOK * TOPK * HEXP];   // routed SwiGLU hidden
__device__ float g_hid_s[NTOK * HSH];           // shared-expert hidden

// ---------------- cp.async helpers ------------------------------------------
__device__ __forceinline__ void cp16(void* dst, const void* src) {
    uint32_t s = (uint32_t)__cvta_generic_to_shared(dst);
    asm volatile("cp.async.cg.shared.global [%0], [%1], 16;"
                 :: "r"(s), "l"(src) : "memory");
}
#define CP_COMMIT() asm volatile("cp.async.commit_group;" ::: "memory")
#define CP_WAIT0()  asm volatile("cp.async.wait_group 0;" ::: "memory")

// ---------------- setup kernels ---------------------------------------------
__global__ void zero_kernel() {
    int t = threadIdx.x;
    if (t < NEXP) g_cnt[t] = 0;
}

__global__ void router_kernel(const float* __restrict__ x,
                              const float* __restrict__ Wg) {
    int gw   = (blockIdx.x * blockDim.x + threadIdx.x) >> 5;
    int lane = threadIdx.x & 31;
    if (gw >= NTOK) return;
    const float* xr = x + (size_t)gw * DMODEL;

    float acc[NEXP];
#pragma unroll
    for (int e = 0; e < NEXP; e++) acc[e] = 0.f;
    for (int k = lane; k < DMODEL; k += 32) {
        float xv = xr[k];
#pragma unroll
        for (int e = 0; e < NEXP; e++) acc[e] += xv * Wg[e * DMODEL + k];
    }
#pragma unroll
    for (int e = 0; e < NEXP; e++) {
#pragma unroll
        for (int o = 16; o > 0; o >>= 1)
            acc[e] += __shfl_xor_sync(0xffffffffu, acc[e], o);
    }
    if (lane == 0) {
        float m = acc[0];
#pragma unroll
        for (int e = 1; e < NEXP; e++) m = fmaxf(m, acc[e]);
        float p[NEXP], s = 0.f;
#pragma unroll
        for (int e = 0; e < NEXP; e++) { p[e] = expf(acc[e] - m); s += p[e]; }
        float inv = 1.f / s;
#pragma unroll
        for (int e = 0; e < NEXP; e++) p[e] *= inv;

        int i0 = 0; float v0 = p[0];
#pragma unroll
        for (int e = 1; e < NEXP; e++) if (p[e] > v0) { v0 = p[e]; i0 = e; }
        int i1 = (i0 == 0) ? 1 : 0; float v1 = p[i1];
#pragma unroll
        for (int e = 0; e < NEXP; e++)
            if (e != i0 && p[e] > v1) { v1 = p[e]; i1 = e; }

        float sw = v0 + v1 + 1e-20f;
        g_topi[gw * 2] = i0;  g_topi[gw * 2 + 1] = i1;
        g_topw[gw * 2] = v0 / sw;  g_topw[gw * 2 + 1] = v1 / sw;
        atomicAdd(&g_cnt[i0], 1);
        atomicAdd(&g_cnt[i1], 1);
    }
}

// single block: exclusive scan of g_cnt, then scatter fill
__global__ void scanfill_kernel() {
    __shared__ int s_off[NEXP + 1];
    __shared__ int s_cur[NEXP];
    int tid = threadIdx.x;
    if (tid == 0) {
        int acc = 0;
        s_off[0] = 0;
        for (int e = 0; e < NEXP; e++) {
            acc += g_cnt[e];
            s_off[e + 1] = acc;
            s_cur[e] = 0;
        }
        for (int e = 0; e <= NEXP; e++) g_off[e] = s_off[e];
    }
    __syncthreads();
    for (int n = tid; n < NTOK; n += blockDim.x) {
#pragma unroll
        for (int s = 0; s < TOPK; s++) {
            int e   = g_topi[n * 2 + s];
            int pos = atomicAdd(&s_cur[e], 1);
            int idx = s_off[e] + pos;
            g_tok[idx]  = n;
            g_gate[idx] = g_topw[n * 2 + s];
        }
    }
}

__device__ __forceinline__ float silu_f(float z) {
    return z / (1.f + __expf(-z));
}

// dynamic-smem layout (floats): As [2][BK][132], then B area.
#define AS_OFF(buf, k)  ((buf) * (BK * 132) + (k) * 132)

// ============ GEMM1 fused: hid = silu(A@W1)*(A@W3) ==========================
// grid (11, 32, 10). CTA 128x64, 256 thr; thread tile 8 rows x 4 cols/matrix.
// BK=32, dynamic smem, 1 barrier per 32-deep tile. A staged in two halves
// inside each tile (STS half0 + LDG half1 hidden under k=16..31 compute).
__global__ __launch_bounds__(256, 2)
void gemm1_all(const float* __restrict__ x,
               const float* __restrict__ W1,
               const float* __restrict__ W3,
               const float* __restrict__ Ws1,
               const float* __restrict__ Ws3) {
    extern __shared__ float sm[];
    float* As  = sm;                        // [2][BK][132]
    float* Bs1 = sm + 2 * BK * 132;         // [2][BK][64]
    float* Bs3 = Bs1 + 2 * BK * 64;         // [2][BK][64]
    __shared__ int stok[128];

    int z = blockIdx.z;
    bool routed = (z < NEXP);
    int base = 0, ne = NTOK, H, n0;
    const float *B1, *B3;
    float* hid;
    if (routed) {
        base = g_off[z]; ne = g_off[z + 1] - base;
        H = HEXP; hid = g_hid_r;
        n0 = blockIdx.x * 64;
        B1 = W1 + (size_t)z * DMODEL * HEXP + n0;
        B3 = W3 + (size_t)z * DMODEL * HEXP + n0;
    } else {
        H = HSH; hid = g_hid_s;
        n0 = (blockIdx.x + (z - NEXP) * 11) * 64;
        B1 = Ws1 + n0;
        B3 = Ws3 + n0;
    }
    int m0 = blockIdx.y * 128;
    if (m0 >= ne) return;

    int tid = threadIdx.x;
    if (tid < 128)
        stok[tid] = routed ? ((m0 + tid < ne) ? g_tok[base + m0 + tid] : -1)
                           : (m0 + tid);
    __syncthreads();

    // A loader: row = tid>>1, k-octet ac = (tid&1)*8 within each 16-half
    int ar = tid >> 1, ac = (tid & 1) * 8;
    int tk = stok[ar];
    bool aok = (tk >= 0);
    const float* Arow = x + (size_t)(aok ? tk : 0) * DMODEL;
    // B loader: k rows br and br+16, chunk bc (one cp16 each per matrix)
    int br = tid >> 4, bc = (tid & 15) * 4;

    float4 av0 = make_float4(0, 0, 0, 0), av1 = make_float4(0, 0, 0, 0);

    // prologue: stage tile 0 (both A halves + B) into buffer 0
#pragma unroll
    for (int h = 0; h < 2; h++) {
        int kb = h * 16;
        if (aok) {
            av0 = *(const float4*)(Arow + kb + ac);
            av1 = *(const float4*)(Arow + kb + ac + 4);
        }
        float* a = As + AS_OFF(0, kb + ac) + ar;
        a[0]     = av0.x; a[132]   = av0.y; a[264]   = av0.z; a[396]   = av0.w;
        a[528]   = av1.x; a[660]   = av1.y; a[792]   = av1.z; a[924]   = av1.w;
    }
    cp16(Bs1 + (size_t)br * 64 + bc,        B1 + (size_t)br * H + bc);
    cp16(Bs1 + (size_t)(br + 16) * 64 + bc, B1 + (size_t)(br + 16) * H + bc);
    cp16(Bs3 + (size_t)br * 64 + bc,        B3 + (size_t)br * H + bc);
    cp16(Bs3 + (size_t)(br + 16) * 64 + bc, B3 + (size_t)(br + 16) * H + bc);
    CP_COMMIT();
    CP_WAIT0();
    __syncthreads();

    int trow = (tid >> 4) * 8, tc = (tid & 15) * 4;
    float acc1[8][4] = {}, acc3[8][4] = {};

    const int NT = DMODEL / BK;
    for (int t = 0; t < NT; t++) {
        int buf = t & 1, nb = buf ^ 1;
        int kn  = (t + 1) * BK;
        bool more = (kn < DMODEL);
        if (more) {
            if (aok) {
                av0 = *(const float4*)(Arow + kn + ac);
                av1 = *(const float4*)(Arow + kn + ac + 4);
            }
            cp16(Bs1 + (size_t)(nb * BK + br) * 64 + bc,
                 B1 + (size_t)(kn + br) * H + bc);
            cp16(Bs1 + (size_t)(nb * BK + br + 16) * 64 + bc,
                 B1 + (size_t)(kn + br + 16) * H + bc);
            cp16(Bs3 + (size_t)(nb * BK + br) * 64 + bc,
                 B3 + (size_t)(kn + br) * H + bc);
            cp16(Bs3 + (size_t)(nb * BK + br + 16) * 64 + bc,
                 B3 + (size_t)(kn + br + 16) * H + bc);
            CP_COMMIT();
        }
        // compute k = 0..15
#pragma unroll
        for (int k = 0; k < 16; k++) {
            const float* ab = As + AS_OFF(buf, k);
            float4 a0 = *(const float4*)(ab + trow);
            float4 a1 = *(const float4*)(ab + trow + 4);
            float4 p  = *(const float4*)(Bs1 + (size_t)(buf * BK + k) * 64 + tc);
            float4 q  = *(const float4*)(Bs3 + (size_t)(buf * BK + k) * 64 + tc);
            float aa[8] = { a0.x, a0.y, a0.z, a0.w, a1.x, a1.y, a1.z, a1.w };
            float pp[4] = { p.x, p.y, p.z, p.w };
            float qq[4] = { q.x, q.y, q.z, q.w };
#pragma unroll
            for (int i = 0; i < 8; i++)
#pragma unroll
                for (int j = 0; j < 4; j++) {
                    acc1[i][j] = fmaf(aa[i], pp[j], acc1[i][j]);
                    acc3[i][j] = fmaf(aa[i], qq[j], acc3[i][j]);
                }
        }
        if (more) {
            // store A half0 of next tile; fetch half1 (hidden under k=16..31)
            float* a = As + AS_OFF(nb, ac) + ar;
            a[0]   = av0.x; a[132] = av0.y; a[264] = av0.z; a[396] = av0.w;
            a[528] = av1.x; a[660] = av1.y; a[792] = av1.z; a[924] = av1.w;
            if (aok) {
                av0 = *(const float4*)(Arow + kn + 16 + ac);
                av1 = *(const float4*)(Arow + kn + 16 + ac + 4);
            }
        }
        // compute k = 16..31
#pragma unroll
        for (int k = 16; k < 32; k++) {
            const float* ab = As + AS_OFF(buf, k);
            float4 a0 = *(const float4*)(ab + trow);
            float4 a1 = *(const float4*)(ab + trow + 4);
            float4 p  = *(const float4*)(Bs1 + (size_t)(buf * BK + k) * 64 + tc);
            float4 q  = *(const float4*)(Bs3 + (size_t)(buf * BK + k) * 64 + tc);
            float aa[8] = { a0.x, a0.y, a0.z, a0.w, a1.x, a1.y, a1.z, a1.w };
            float pp[4] = { p.x, p.y, p.z, p.w };
            float qq[4] = { q.x, q.y, q.z, q.w };
#pragma unroll
            for (int i = 0; i < 8; i++)
#pragma unroll
                for (int j = 0; j < 4; j++) {
                    acc1[i][j] = fmaf(aa[i], pp[j], acc1[i][j]);
                    acc3[i][j] = fmaf(aa[i], qq[j], acc3[i][j]);
                }
        }
        if (more) {
            float* a = As + AS_OFF(nb, 16 + ac) + ar;
            a[0]   = av0.x; a[132] = av0.y; a[264] = av0.z; a[396] = av0.w;
            a[528] = av1.x; a[660] = av1.y; a[792] = av1.z; a[924] = av1.w;
            CP_WAIT0();
        }
        __syncthreads();
    }

#pragma unroll
    for (int i = 0; i < 8; i++) {
        int r = trow + i;
        if (m0 + r < ne) {
            float4 hv;
            hv.x = silu_f(acc1[i][0]) * acc3[i][0];
            hv.y = silu_f(acc1[i][1]) * acc3[i][1];
            hv.z = silu_f(acc1[i][2]) * acc3[i][2];
            hv.w = silu_f(acc1[i][3]) * acc3[i][3];
            *(float4*)&hid[(size_t)(base + m0 + r) * H + n0 + tc] = hv;
        }
    }
}

// ============ GEMM2 fused: out += w * (hid @ W2) ============================
// grid (8, 32, 9). CTA 128x128, 256 thr; thread tile 8 rows x (4+4) cols.
// BK=32, dynamic smem, two-phase A staging. out pre-zeroed, atomicAdd.
__global__ __launch_bounds__(256, 2)
void gemm2_all(const float* __restrict__ W2,
               const float* __restrict__ Ws2,
               float* __restrict__ out) {
    extern __shared__ float sm[];
    float* As = sm;                 // [2][BK][132]
    float* Bs = sm + 2 * BK * 132;  // [2][BK][128]
    __shared__ int   stok[128];
    __shared__ float sgate[128];

    int z = blockIdx.z;
    bool routed = (z < NEXP);
    int base = 0, ne = NTOK, K;
    const float* Bp;
    const float* hidg;
    int n0 = blockIdx.x * 128;
    if (routed) {
        base = g_off[z]; ne = g_off[z + 1] - base;
        K = HEXP; hidg = g_hid_r;
        Bp = W2 + (size_t)z * HEXP * DMODEL + n0;
    } else {
        K = HSH; hidg = g_hid_s;
        Bp = Ws2 + n0;
    }
    int m0 = blockIdx.y * 128;
    if (m0 >= ne) return;

    int tid = threadIdx.x;
    if (tid < 128) {
        if (routed) {
            bool v = (m0 + tid < ne);
            stok[tid]  = v ? g_tok[base + m0 + tid] : 0;
            sgate[tid] = v ? g_gate[base + m0 + tid] : 0.f;
        } else {
            stok[tid]  = m0 + tid;
            sgate[tid] = 1.f;
        }
    }
    __syncthreads();

    int ar = tid >> 1, ac = (tid & 1) * 8;
    bool aok = (m0 + ar < ne);
    const float* Arow = hidg + (size_t)(base + m0 + (aok ? ar : 0)) * K;
    int br = tid >> 4, bc = (tid & 15) * 4;

    float4 av0 = make_float4(0, 0, 0, 0), av1 = make_float4(0, 0, 0, 0);

#pragma unroll
    for (int h = 0; h < 2; h++) {
        int kb = h * 16;
        if (aok) {
            av0 = *(const float4*)(Arow + kb + ac);
            av1 = *(const float4*)(Arow + kb + ac + 4);
        }
        float* a = As + AS_OFF(0, kb + ac) + ar;
        a[0]   = av0.x; a[132] = av0.y; a[264] = av0.z; a[396] = av0.w;
        a[528] = av1.x; a[660] = av1.y; a[792] = av1.z; a[924] = av1.w;
    }
    cp16(Bs + (size_t)br * 128 + bc,             Bp + (size_t)br * DMODEL + bc);
    cp16(Bs + (size_t)br * 128 + bc + 64,        Bp + (size_t)br * DMODEL + bc + 64);
    cp16(Bs + (size_t)(br + 16) * 128 + bc,      Bp + (size_t)(br + 16) * DMODEL + bc);
    cp16(Bs + (size_t)(br + 16) * 128 + bc + 64, Bp + (size_t)(br + 16) * DMODEL + bc + 64);
    CP_COMMIT();
    CP_WAIT0();
    __syncthreads();

    int trow = (tid >> 4) * 8, tc = (tid & 15) * 4;
    float acc[8][8] = {};

    const int NT_ = K / BK;
    for (int t = 0; t < NT_; t++) {
        int buf = t & 1, nb = buf ^ 1;
        int kn  = (t + 1) * BK;
        bool more = (kn < K);
        if (more) {
            if (aok) {
                av0 = *(const float4*)(Arow + kn + ac);
                av1 = *(const float4*)(Arow + kn + ac + 4);
            }
            cp16(Bs + (size_t)(nb * BK + br) * 128 + bc,
                 Bp + (size_t)(kn + br) * DMODEL + bc);
            cp16(Bs + (size_t)(nb * BK + br) * 128 + bc + 64,
                 Bp + (size_t)(kn + br) * DMODEL + bc + 64);
            cp16(Bs + (size_t)(nb * BK + br + 16) * 128 + bc,
                 Bp + (size_t)(kn + br + 16) * DMODEL + bc);
            cp16(Bs + (size_t)(nb * BK + br + 16) * 128 + bc + 64,
                 Bp + (size_t)(kn + br + 16) * DMODEL + bc + 64);
            CP_COMMIT();
        }
#pragma unroll
        for (int k = 0; k < 16; k++) {
            const float* ab = As + AS_OFF(buf, k);
            float4 a0 = *(const float4*)(ab + trow);
            float4 a1 = *(const float4*)(ab + trow + 4);
            float4 b0 = *(const float4*)(Bs + (size_t)(buf * BK + k) * 128 + tc);
            float4 b1 = *(const float4*)(Bs + (size_t)(buf * BK + k) * 128 + tc + 64);
            float aa[8] = { a0.x, a0.y, a0.z, a0.w, a1.x, a1.y, a1.z, a1.w };
            float bb[8] = { b0.x, b0.y, b0.z, b0.w, b1.x, b1.y, b1.z, b1.w };
#pragma unroll
            for (int i = 0; i < 8; i++)
#pragma unroll
                for (int j = 0; j < 8; j++)
                    acc[i][j] = fmaf(aa[i], bb[j], acc[i][j]);
        }
        if (more) {
            float* a = As + AS_OFF(nb, ac) + ar;
            a[0]   = av0.x; a[132] = av0.y; a[264] = av0.z; a[396] = av0.w;
            a[528] = av1.x; a[660] = av1.y; a[792] = av1.z; a[924] = av1.w;
            if (aok) {
                av0 = *(const float4*)(Arow + kn + 16 + ac);
                av1 = *(const float4*)(Arow + kn + 16 + ac + 4);
            }
        }
#pragma unroll
        for (int k = 16; k < 32; k++) {
            const float* ab = As + AS_OFF(buf, k);
            float4 a0 = *(const float4*)(ab + trow);
            float4 a1 = *(const float4*)(ab + trow + 4);
            float4 b0 = *(const float4*)(Bs + (size_t)(buf * BK + k) * 128 + tc);
            float4 b1 = *(const float4*)(Bs + (size_t)(buf * BK + k) * 128 + tc + 64);
            float aa[8] = { a0.x, a0.y, a0.z, a0.w, a1.x, a1.y, a1.z, a1.w };
            float bb[8] = { b0.x, b0.y, b0.z, b0.w, b1.x, b1.y, b1.z, b1.w };
#pragma unroll
            for (int i = 0; i < 8; i++)
#pragma unroll
                for (int j = 0; j < 8; j++)
                    acc[i][j] = fmaf(aa[i], bb[j], acc[i][j]);
        }
        if (more) {
            float* a = As + AS_OFF(nb, 16 + ac) + ar;
            a[0]   = av0.x; a[132] = av0.y; a[264] = av0.z; a[396] = av0.w;
            a[528] = av1.x; a[660] = av1.y; a[792] = av1.z; a[924] = av1.w;
            CP_WAIT0();
        }
        __syncthreads();
    }

#pragma unroll
    for (int i = 0; i < 8; i++) {
        int r = trow + i;
        if (m0 + r < ne) {
            int   tk = stok[r];
            float w  = sgate[r];
            float* op = out + (size_t)tk * DMODEL + n0;
#pragma unroll
            for (int j = 0; j < 4; j++) {
                atomicAdd(op + tc + j,      w * acc[i][j]);
                atomicAdd(op + tc + 64 + j, w * acc[i][j + 4]);
            }
        }
    }
}

// ---------------- launch -----------------------------------------------------
extern "C" void kernel_launch(void* const* d_in, const int* in_sizes, int n_in,
                              void* d_out, int out_size) {
    const float* x   = (const float*)d_in[0];
    const float* Wg  = (const float*)d_in[1];
    const float* W1  = (const float*)d_in[2];
    const float* W3  = (const float*)d_in[3];
    const float* W2  = (const float*)d_in[4];
    const float* Ws1 = (const float*)d_in[5];
    const float* Ws3 = (const float*)d_in[6];
    const float* Ws2 = (const float*)d_in[7];
    float* out = (float*)d_out;

    const int SMEM1 = (2 * BK * 132 + 2 * 2 * BK * 64) * 4;   // 66560 B
    const int SMEM2 = (2 * BK * 132 + 2 * BK * 128) * 4;      // 66560 B
    static bool attr_done = false;
    if (!attr_done) {
        cudaFuncSetAttribute(gemm1_all,
            cudaFuncAttributeMaxDynamicSharedMemorySize, SMEM1);
        cudaFuncSetAttribute(gemm2_all,
            cudaFuncAttributeMaxDynamicSharedMemorySize, SMEM2);
        attr_done = true;
    }

    cudaMemsetAsync(out, 0, (size_t)NTOK * DMODEL * sizeof(float));
    zero_kernel<<<1, 32>>>();
    router_kernel<<<NTOK / 8, 256>>>(x, Wg);
    scanfill_kernel<<<1, 1024>>>();

    // fused up-proj: routed (z=0..7) + shared halves (z=8,9)
    gemm1_all<<<dim3(HEXP / 64, NTOK / 128, 10), 256, SMEM1>>>(x, W1, W3, Ws1, Ws3);
    // fused down-proj: routed (z=0..7) + shared (z=8), all atomic into out
    gemm2_all<<<dim3(DMODEL / 128, NTOK / 128, 9), 256, SMEM2>>>(W2, Ws2, out);
}